// round 2
// baseline (speedup 1.0000x reference)
#include <cuda_runtime.h>
#include <math_constants.h>

#define NN 80000
#define NE 1280000
#define SCAN_B 1024
#define NB ((NN + SCAN_B - 1) / SCAN_B)   // 79
#define NBLK_N ((NN + 255) / 256)         // 313
#define NBLK_E ((NE + 255) / 256)         // 5000
#define BN_EPS 1e-5f
#define SLOPE 0.01f

// ---------------- persistent device scratch ----------------
__device__ int   g_deg[NN];
__device__ int   g_cnt[NN];
__device__ int   g_rowptr[NN + 1];
__device__ int   g_bsum[NB];
__device__ int   g_srcs[NE];
__device__ float g_dinv[NN];
__device__ __align__(16) float g_h[NN * 64];
__device__ __align__(16) float g_y[NN * 64];
__device__ __align__(16) float g_x[NN * 64];
__device__ float g_part[256 * 128];   // [block][0..63]=sum, [64..127]=sumsq
__device__ float g_scale[64];
__device__ float g_shift[64];

// ---------------- CSR build ----------------
__global__ void k_zero() {
    int i = blockIdx.x * blockDim.x + threadIdx.x;
    if (i < NN) { g_deg[i] = 0; g_cnt[i] = 0; }
}

__global__ void k_hist(const int* __restrict__ dst) {
    int e = blockIdx.x * blockDim.x + threadIdx.x;
    if (e < NE) {
        int d = dst[e];
        if ((unsigned)d < NN) atomicAdd(&g_deg[d], 1);
    }
}

__global__ void k_dinv() {
    int i = blockIdx.x * blockDim.x + threadIdx.x;
    if (i < NN) g_dinv[i] = rsqrtf((float)g_deg[i] + 2.0f);
}

__global__ void k_scan1() {
    __shared__ int wsum[32];
    int i = blockIdx.x * SCAN_B + threadIdx.x;
    int v = (i < NN) ? g_deg[i] : 0;
    int lane = threadIdx.x & 31, wid = threadIdx.x >> 5;
    int s = v;
    #pragma unroll
    for (int o = 1; o < 32; o <<= 1) {
        int t = __shfl_up_sync(0xffffffffu, s, o);
        if (lane >= o) s += t;
    }
    if (lane == 31) wsum[wid] = s;
    __syncthreads();
    if (wid == 0) {
        int ws = wsum[lane];
        #pragma unroll
        for (int o = 1; o < 32; o <<= 1) {
            int t = __shfl_up_sync(0xffffffffu, ws, o);
            if (lane >= o) ws += t;
        }
        wsum[lane] = ws;
    }
    __syncthreads();
    int off = (wid > 0) ? wsum[wid - 1] : 0;
    int incl = s + off;
    if (i < NN) g_rowptr[i] = incl - v;              // block-local exclusive
    if (threadIdx.x == SCAN_B - 1) g_bsum[blockIdx.x] = incl;  // block total
}

__global__ void k_scan2() {
    if (threadIdx.x == 0) {
        int run = 0;
        for (int b = 0; b < NB; b++) { int t = g_bsum[b]; g_bsum[b] = run; run += t; }
    }
}

__global__ void k_scan3() {
    int i = blockIdx.x * SCAN_B + threadIdx.x;
    if (i < NN) g_rowptr[i] += g_bsum[blockIdx.x];
    if (blockIdx.x == 0 && threadIdx.x == 0) g_rowptr[NN] = NE;
}

__global__ void k_fill(const int* __restrict__ src,
                       const int* __restrict__ dst) {
    int e = blockIdx.x * blockDim.x + threadIdx.x;
    if (e < NE) {
        int d = dst[e];
        int s = src[e];
        if ((unsigned)d < NN && (unsigned)s < NN) {
            int p = g_rowptr[d] + atomicAdd(&g_cnt[d], 1);
            if ((unsigned)p < NE) g_srcs[p] = s;
        }
    }
}

// ---------------- dense: h = x @ W ----------------
template <int CIN, int COUT, bool FROMG>
__global__ void k_mm(const float* __restrict__ xin, const float* __restrict__ W) {
    __shared__ __align__(16) float Ws[CIN * COUT];
    for (int i = threadIdx.x; i < CIN * COUT; i += blockDim.x) Ws[i] = W[i];
    __syncthreads();
    int n = blockIdx.x * blockDim.x + threadIdx.x;
    if (n >= NN) return;
    const float* x = FROMG ? g_x : xin;

    float xr[CIN];
    if constexpr (CIN % 4 == 0) {
        const float4* xv = (const float4*)&x[n * CIN];
        #pragma unroll
        for (int i = 0; i < CIN / 4; i++) {
            float4 v = xv[i];
            xr[4 * i] = v.x; xr[4 * i + 1] = v.y; xr[4 * i + 2] = v.z; xr[4 * i + 3] = v.w;
        }
    } else {
        #pragma unroll
        for (int i = 0; i < CIN; i++) xr[i] = x[n * CIN + i];
    }

    if constexpr (COUT % 4 == 0) {
        for (int j0 = 0; j0 < COUT; j0 += 4) {
            float ax = 0.f, ay = 0.f, az = 0.f, aw = 0.f;
            #pragma unroll
            for (int i = 0; i < CIN; i++) {
                float4 w = *(const float4*)&Ws[i * COUT + j0];
                ax = fmaf(xr[i], w.x, ax); ay = fmaf(xr[i], w.y, ay);
                az = fmaf(xr[i], w.z, az); aw = fmaf(xr[i], w.w, aw);
            }
            float4 o; o.x = ax; o.y = ay; o.z = az; o.w = aw;
            *(float4*)&g_h[n * COUT + j0] = o;
        }
    } else {
        #pragma unroll
        for (int j = 0; j < COUT; j++) {
            float a = 0.f;
            #pragma unroll
            for (int i = 0; i < CIN; i++) a = fmaf(xr[i], Ws[i * COUT + j], a);
            g_h[n * COUT + j] = a;
        }
    }
}

// ---------------- aggregation: y = deg-normalized gather + self + bias ----------------
template <int COUT>
__global__ void k_agg(const float* __restrict__ bias) {
    constexpr int WPN = (COUT > 32) ? 2 : 1;   // warps per node
    int gw = (blockIdx.x * blockDim.x + threadIdx.x) >> 5;
    int lane = threadIdx.x & 31;
    int n = gw / WPN;
    int half = gw - n * WPN;
    if (n >= NN) return;
    int ch = half * 32 + lane;
    bool act = ch < COUT;

    int beg = g_rowptr[n], end = g_rowptr[n + 1];
    float dn = g_dinv[n];
    float acc = 0.f;

    int e = beg;
    for (; e + 4 <= end; e += 4) {
        int s0 = g_srcs[e],     s1 = g_srcs[e + 1];
        int s2 = g_srcs[e + 2], s3 = g_srcs[e + 3];
        float w0 = g_dinv[s0], w1 = g_dinv[s1], w2 = g_dinv[s2], w3 = g_dinv[s3];
        float h0 = 0.f, h1 = 0.f, h2 = 0.f, h3 = 0.f;
        if (act) {
            h0 = g_h[s0 * COUT + ch]; h1 = g_h[s1 * COUT + ch];
            h2 = g_h[s2 * COUT + ch]; h3 = g_h[s3 * COUT + ch];
        }
        acc = fmaf(h0, w0, acc); acc = fmaf(h1, w1, acc);
        acc = fmaf(h2, w2, acc); acc = fmaf(h3, w3, acc);
    }
    for (; e < end; e++) {
        int s = g_srcs[e];
        float w = g_dinv[s];
        if (act) acc = fmaf(g_h[s * COUT + ch], w, acc);
    }

    if (act) {
        acc *= dn;                                    // norm = dinv[src]*dinv[dst]
        acc = fmaf(2.f * dn * dn, g_h[n * COUT + ch], acc);  // self loop (improved=True)
        acc += bias[ch];
        g_y[n * COUT + ch] = acc;
    }
}

// ---------------- BN stats pass 1 (deterministic partials) ----------------
template <int C>
__global__ void k_red() {
    constexpr int CP = (C > 4) ? C : 4;       // padded channel slots per row
    constexpr int RPB = 256 / CP;             // rows per block per sweep
    int c = threadIdx.x % CP;
    int r = threadIdx.x / CP;
    float s = 0.f, q = 0.f;
    if (c < C) {
        for (int n = blockIdx.x * RPB + r; n < NN; n += 256 * RPB) {
            float v = g_y[n * C + c];
            s += v; q = fmaf(v, v, q);
        }
    }
    __shared__ float ss[256], sq[256];
    ss[threadIdx.x] = s; sq[threadIdx.x] = q;
    __syncthreads();
    if (r == 0 && c < C) {
        for (int k = 1; k < RPB; k++) { s += ss[k * CP + c]; q += sq[k * CP + c]; }
        g_part[blockIdx.x * 128 + c]      = s;
        g_part[blockIdx.x * 128 + 64 + c] = q;
    }
}

// ---------------- BN stats pass 2: scale/shift ----------------
template <int C>
__global__ void k_stats(const float* __restrict__ gamma, const float* __restrict__ beta) {
    int c = threadIdx.x;
    if (c >= C) return;
    float s = 0.f, q = 0.f;
    for (int b = 0; b < 256; b++) {
        s += g_part[b * 128 + c];
        q += g_part[b * 128 + 64 + c];
    }
    float mean = s * (1.0f / NN);
    float var = q * (1.0f / NN) - mean * mean;
    float sc = gamma[c] * rsqrtf(var + BN_EPS);
    g_scale[c] = sc;
    g_shift[c] = beta[c] - mean * sc;
}

// ---------------- BN apply + maxpool + lrelu + linear + lrelu ----------------
template <int C, int PK, int PP, bool TOOUT>
__global__ void k_post(const float* __restrict__ lw, const float* __restrict__ lb,
                       float* __restrict__ outp) {
    __shared__ __align__(16) float lws[C * C];
    __shared__ float lbs[C], sc[C], sh[C];
    for (int i = threadIdx.x; i < C * C; i += blockDim.x) lws[i] = lw[i];
    if (threadIdx.x < C) {
        lbs[threadIdx.x] = lb[threadIdx.x];
        sc[threadIdx.x]  = g_scale[threadIdx.x];
        sh[threadIdx.x]  = g_shift[threadIdx.x];
    }
    __syncthreads();
    int n = blockIdx.x * blockDim.x + threadIdx.x;
    if (n >= NN) return;
    float* out = TOOUT ? outp : g_x;

    float t[C];
    if constexpr (C % 4 == 0) {
        const float4* yv = (const float4*)&g_y[n * C];
        #pragma unroll
        for (int i = 0; i < C / 4; i++) {
            float4 v = yv[i];
            t[4 * i]     = fmaf(v.x, sc[4 * i],     sh[4 * i]);
            t[4 * i + 1] = fmaf(v.y, sc[4 * i + 1], sh[4 * i + 1]);
            t[4 * i + 2] = fmaf(v.z, sc[4 * i + 2], sh[4 * i + 2]);
            t[4 * i + 3] = fmaf(v.w, sc[4 * i + 3], sh[4 * i + 3]);
        }
    } else {
        #pragma unroll
        for (int c = 0; c < C; c++) t[c] = fmaf(g_y[n * C + c], sc[c], sh[c]);
    }

    float m[C];
    #pragma unroll
    for (int c = 0; c < C; c++) {
        int lo = c - PP; if (lo < 0) lo = 0;
        int hi = c - PP + PK - 1; if (hi > C - 1) hi = C - 1;
        float mx = t[lo];
        #pragma unroll
        for (int d = 0; d < PK; d++) {
            int idx = c - PP + d;
            if (idx > lo && idx <= hi) mx = fmaxf(mx, t[idx]);
        }
        m[c] = (mx >= 0.f) ? mx : SLOPE * mx;   // leaky relu after pool
    }

    if constexpr (C % 4 == 0) {
        for (int j0 = 0; j0 < C; j0 += 4) {
            float a0 = lbs[j0], a1 = lbs[j0 + 1], a2 = lbs[j0 + 2], a3 = lbs[j0 + 3];
            #pragma unroll
            for (int c = 0; c < C; c += 4) {
                float4 w0 = *(const float4*)&lws[(j0    ) * C + c];
                float4 w1 = *(const float4*)&lws[(j0 + 1) * C + c];
                float4 w2 = *(const float4*)&lws[(j0 + 2) * C + c];
                float4 w3 = *(const float4*)&lws[(j0 + 3) * C + c];
                a0 = fmaf(m[c], w0.x, a0); a0 = fmaf(m[c+1], w0.y, a0); a0 = fmaf(m[c+2], w0.z, a0); a0 = fmaf(m[c+3], w0.w, a0);
                a1 = fmaf(m[c], w1.x, a1); a1 = fmaf(m[c+1], w1.y, a1); a1 = fmaf(m[c+2], w1.z, a1); a1 = fmaf(m[c+3], w1.w, a1);
                a2 = fmaf(m[c], w2.x, a2); a2 = fmaf(m[c+1], w2.y, a2); a2 = fmaf(m[c+2], w2.z, a2); a2 = fmaf(m[c+3], w2.w, a2);
                a3 = fmaf(m[c], w3.x, a3); a3 = fmaf(m[c+1], w3.y, a3); a3 = fmaf(m[c+2], w3.z, a3); a3 = fmaf(m[c+3], w3.w, a3);
            }
            float4 o;
            o.x = (a0 >= 0.f) ? a0 : SLOPE * a0;
            o.y = (a1 >= 0.f) ? a1 : SLOPE * a1;
            o.z = (a2 >= 0.f) ? a2 : SLOPE * a2;
            o.w = (a3 >= 0.f) ? a3 : SLOPE * a3;
            *(float4*)&out[n * C + j0] = o;
        }
    } else {
        #pragma unroll
        for (int j = 0; j < C; j++) {
            float a = lbs[j];
            #pragma unroll
            for (int c = 0; c < C; c++) a = fmaf(m[c], lws[j * C + c], a);
            out[n * C + j] = (a >= 0.f) ? a : SLOPE * a;
        }
    }
}

// ---------------- launch ----------------
extern "C" void kernel_launch(void* const* d_in, const int* in_sizes, int n_in,
                              void* d_out, int out_size) {
    const float* x   = (const float*)d_in[0];
    const int*   ei  = (const int*)d_in[1];      // JAX default: int64 request -> int32 array
    const int*   src = ei;
    const int*   dst = ei + NE;
    const float *w0 = (const float*)d_in[2],  *b0 = (const float*)d_in[3];
    const float *g0 = (const float*)d_in[4],  *bb0 = (const float*)d_in[5];
    const float *lw0 = (const float*)d_in[6], *lb0 = (const float*)d_in[7];
    const float *w1 = (const float*)d_in[8],  *b1 = (const float*)d_in[9];
    const float *g1 = (const float*)d_in[10], *bb1 = (const float*)d_in[11];
    const float *lw1 = (const float*)d_in[12], *lb1 = (const float*)d_in[13];
    const float *w2 = (const float*)d_in[14], *b2 = (const float*)d_in[15];
    const float *g2 = (const float*)d_in[16], *bb2 = (const float*)d_in[17];
    const float *lw2 = (const float*)d_in[18], *lb2 = (const float*)d_in[19];
    float* out = (float*)d_out;

    // CSR build (per replay; deterministic up to fp-irrelevant slot ordering)
    k_zero<<<NBLK_N, 256>>>();
    k_hist<<<NBLK_E, 256>>>(dst);
    k_dinv<<<NBLK_N, 256>>>();
    k_scan1<<<NB, SCAN_B>>>();
    k_scan2<<<1, 32>>>();
    k_scan3<<<NB, SCAN_B>>>();
    k_fill<<<NBLK_E, 256>>>(src, dst);

    const int aggblk64 = (NN * 2 * 32 + 255) / 256;  // 20000
    const int aggblk3  = (NN * 32 + 255) / 256;      // 10000

    // stage 0: 3 -> 64, pool k=3 p=1
    k_mm<3, 64, false><<<NBLK_N, 256>>>(x, w0);
    k_agg<64><<<aggblk64, 256>>>(b0);
    k_red<64><<<256, 256>>>();
    k_stats<64><<<1, 64>>>(g0, bb0);
    k_post<64, 3, 1, false><<<NBLK_N, 256>>>(lw0, lb0, nullptr);

    // stage 1: 64 -> 64, pool k=5 p=2
    k_mm<64, 64, true><<<NBLK_N, 256>>>(nullptr, w1);
    k_agg<64><<<aggblk64, 256>>>(b1);
    k_red<64><<<256, 256>>>();
    k_stats<64><<<1, 64>>>(g1, bb1);
    k_post<64, 5, 2, false><<<NBLK_N, 256>>>(lw1, lb1, nullptr);

    // stage 2: 64 -> 3, pool k=3 p=1
    k_mm<64, 3, true><<<NBLK_N, 256>>>(nullptr, w2);
    k_agg<3><<<aggblk3, 256>>>(b2);
    k_red<3><<<256, 256>>>();
    k_stats<3><<<1, 64>>>(g2, bb2);
    k_post<3, 3, 1, true><<<NBLK_N, 256>>>(lw2, lb2, out);
}

// round 3
// speedup vs baseline: 1.1389x; 1.1389x over previous
#include <cuda_runtime.h>
#include <math_constants.h>

#define NN 80000
#define NE 1280000
#define SCAN_B 1024
#define NB ((NN + SCAN_B - 1) / SCAN_B)   // 79
#define NBLK_N ((NN + 255) / 256)         // 313
#define NBLK_E ((NE + 255) / 256)         // 5000
#define AGG_BLK ((NN * 32 + 255) / 256)   // 10000 (warp per node)
#define BN_EPS 1e-5f
#define SLOPE 0.01f

// ---------------- persistent device scratch ----------------
__device__ int   g_deg[NN];
__device__ int   g_cnt[NN];
__device__ int   g_rowptr[NN + 1];
__device__ int   g_bsum[NB];
__device__ int   g_srcs[NE];
__device__ float g_dinv[NN];
__device__ __align__(16) float g_h[NN * 64];
__device__ __align__(16) float g_y[NN * 64];
__device__ __align__(16) float g_x[NN * 64];
__device__ __align__(16) float g_z[NN * 3];
__device__ float g_part[256 * 128];   // [block][0..63]=sum, [64..127]=sumsq
__device__ float g_scale[64];
__device__ float g_shift[64];
__device__ int   g_rcount = 0;

// ---------------- CSR build ----------------
__global__ void k_zero() {
    int i = blockIdx.x * blockDim.x + threadIdx.x;
    if (i < NN) { g_deg[i] = 0; g_cnt[i] = 0; }
}

__global__ void k_hist(const int* __restrict__ dst) {
    int i = blockIdx.x * blockDim.x + threadIdx.x;
    if (i < NE / 4) {
        int4 d = ((const int4*)dst)[i];
        if ((unsigned)d.x < NN) atomicAdd(&g_deg[d.x], 1);
        if ((unsigned)d.y < NN) atomicAdd(&g_deg[d.y], 1);
        if ((unsigned)d.z < NN) atomicAdd(&g_deg[d.z], 1);
        if ((unsigned)d.w < NN) atomicAdd(&g_deg[d.w], 1);
    }
}

__global__ void k_scan1() {
    __shared__ int wsum[32];
    int i = blockIdx.x * SCAN_B + threadIdx.x;
    int v = (i < NN) ? g_deg[i] : 0;
    if (i < NN) g_dinv[i] = rsqrtf((float)v + 2.0f);   // fused dinv
    int lane = threadIdx.x & 31, wid = threadIdx.x >> 5;
    int s = v;
    #pragma unroll
    for (int o = 1; o < 32; o <<= 1) {
        int t = __shfl_up_sync(0xffffffffu, s, o);
        if (lane >= o) s += t;
    }
    if (lane == 31) wsum[wid] = s;
    __syncthreads();
    if (wid == 0) {
        int ws = wsum[lane];
        #pragma unroll
        for (int o = 1; o < 32; o <<= 1) {
            int t = __shfl_up_sync(0xffffffffu, ws, o);
            if (lane >= o) ws += t;
        }
        wsum[lane] = ws;
    }
    __syncthreads();
    int off = (wid > 0) ? wsum[wid - 1] : 0;
    int incl = s + off;
    if (i < NN) g_rowptr[i] = incl - v;
    if (threadIdx.x == SCAN_B - 1) g_bsum[blockIdx.x] = incl;
}

__global__ void k_scan2() {
    if (threadIdx.x == 0) {
        int run = 0;
        for (int b = 0; b < NB; b++) { int t = g_bsum[b]; g_bsum[b] = run; run += t; }
    }
}

__global__ void k_scan3() {
    int i = blockIdx.x * SCAN_B + threadIdx.x;
    if (i < NN) g_rowptr[i] += g_bsum[blockIdx.x];
    if (blockIdx.x == 0 && threadIdx.x == 0) g_rowptr[NN] = NE;
}

__global__ void k_fill(const int* __restrict__ src,
                       const int* __restrict__ dst) {
    int e = blockIdx.x * blockDim.x + threadIdx.x;
    if (e < NE) {
        int d = dst[e];
        int s = src[e];
        if ((unsigned)d < NN && (unsigned)s < NN) {
            int p = g_rowptr[d] + atomicAdd(&g_cnt[d], 1);
            if ((unsigned)p < NE) g_srcs[p] = s;
        }
    }
}

// ---------------- 3-channel aggregation (warp per node) ----------------
// FROMH=false: feat = xin (stage 0 raw input), out = g_z, no bias
// FROMH=true : feat = g_h (stage 2 post-W),    out = g_y, + bias
template <bool FROMH>
__global__ void k_agg3(const float* __restrict__ xin, const float* __restrict__ bias) {
    int gw = (blockIdx.x * blockDim.x + threadIdx.x) >> 5;
    int lane = threadIdx.x & 31;
    if (gw >= NN) return;
    const float* feat = FROMH ? (const float*)g_h : xin;

    int beg = g_rowptr[gw], end = g_rowptr[gw + 1];
    float a0 = 0.f, a1 = 0.f, a2 = 0.f;
    for (int e = beg + lane; e < end; e += 32) {
        int s = g_srcs[e];
        float w = g_dinv[s];
        a0 = fmaf(feat[s * 3 + 0], w, a0);
        a1 = fmaf(feat[s * 3 + 1], w, a1);
        a2 = fmaf(feat[s * 3 + 2], w, a2);
    }
    #pragma unroll
    for (int o = 16; o; o >>= 1) {
        a0 += __shfl_down_sync(0xffffffffu, a0, o);
        a1 += __shfl_down_sync(0xffffffffu, a1, o);
        a2 += __shfl_down_sync(0xffffffffu, a2, o);
    }
    if (lane == 0) {
        float dn = g_dinv[gw];
        float st = 2.f * dn * dn;
        float o0 = fmaf(a0, dn, st * feat[gw * 3 + 0]);
        float o1 = fmaf(a1, dn, st * feat[gw * 3 + 1]);
        float o2 = fmaf(a2, dn, st * feat[gw * 3 + 2]);
        if (FROMH) {
            g_y[gw * 3 + 0] = o0 + bias[0];
            g_y[gw * 3 + 1] = o1 + bias[1];
            g_y[gw * 3 + 2] = o2 + bias[2];
        } else {
            g_z[gw * 3 + 0] = o0;
            g_z[gw * 3 + 1] = o1;
            g_z[gw * 3 + 2] = o2;
        }
    }
}

// ---------------- 64-channel aggregation (warp per node, float2/lane) ----------------
__global__ void k_agg64(const float* __restrict__ bias) {
    int gw = (blockIdx.x * blockDim.x + threadIdx.x) >> 5;
    int lane = threadIdx.x & 31;
    if (gw >= NN) return;

    int beg = g_rowptr[gw], end = g_rowptr[gw + 1];
    float ax = 0.f, ay = 0.f;
    int e = beg;
    for (; e + 4 <= end; e += 4) {
        int s0 = g_srcs[e],     s1 = g_srcs[e + 1];
        int s2 = g_srcs[e + 2], s3 = g_srcs[e + 3];
        float w0 = g_dinv[s0], w1 = g_dinv[s1], w2 = g_dinv[s2], w3 = g_dinv[s3];
        float2 h0 = ((const float2*)&g_h[s0 * 64])[lane];
        float2 h1 = ((const float2*)&g_h[s1 * 64])[lane];
        float2 h2 = ((const float2*)&g_h[s2 * 64])[lane];
        float2 h3 = ((const float2*)&g_h[s3 * 64])[lane];
        ax = fmaf(h0.x, w0, ax); ay = fmaf(h0.y, w0, ay);
        ax = fmaf(h1.x, w1, ax); ay = fmaf(h1.y, w1, ay);
        ax = fmaf(h2.x, w2, ax); ay = fmaf(h2.y, w2, ay);
        ax = fmaf(h3.x, w3, ax); ay = fmaf(h3.y, w3, ay);
    }
    for (; e < end; e++) {
        int s = g_srcs[e];
        float w = g_dinv[s];
        float2 h = ((const float2*)&g_h[s * 64])[lane];
        ax = fmaf(h.x, w, ax); ay = fmaf(h.y, w, ay);
    }

    float dn = g_dinv[gw];
    float st = 2.f * dn * dn;
    float2 hs = ((const float2*)&g_h[gw * 64])[lane];
    float2 bv = ((const float2*)bias)[lane];
    float2 o;
    o.x = fmaf(ax, dn, fmaf(st, hs.x, bv.x));
    o.y = fmaf(ay, dn, fmaf(st, hs.y, bv.y));
    ((float2*)&g_y[gw * 64])[lane] = o;
}

// ---------------- dense: out = src @ W (+bias) ----------------
// SRCSEL: 0 = xin arg, 1 = g_x, 2 = g_z.   OUTY: true -> g_y (+bias), false -> g_h
template <int CIN, int COUT, int SRCSEL, bool OUTY>
__global__ void k_mm(const float* __restrict__ xin, const float* __restrict__ W,
                     const float* __restrict__ bias) {
    __shared__ __align__(16) float Ws[CIN * COUT];
    for (int i = threadIdx.x; i < CIN * COUT; i += blockDim.x) Ws[i] = W[i];
    __syncthreads();
    int n = blockIdx.x * blockDim.x + threadIdx.x;
    if (n >= NN) return;
    const float* x = (SRCSEL == 0) ? xin : (SRCSEL == 1) ? (const float*)g_x : (const float*)g_z;
    float* out = OUTY ? g_y : g_h;

    float xr[CIN];
    if constexpr (CIN % 4 == 0) {
        const float4* xv = (const float4*)&x[n * CIN];
        #pragma unroll
        for (int i = 0; i < CIN / 4; i++) {
            float4 v = xv[i];
            xr[4 * i] = v.x; xr[4 * i + 1] = v.y; xr[4 * i + 2] = v.z; xr[4 * i + 3] = v.w;
        }
    } else {
        #pragma unroll
        for (int i = 0; i < CIN; i++) xr[i] = x[n * CIN + i];
    }

    if constexpr (COUT % 4 == 0) {
        for (int j0 = 0; j0 < COUT; j0 += 4) {
            float ax, ay, az, aw;
            if (OUTY) { ax = bias[j0]; ay = bias[j0 + 1]; az = bias[j0 + 2]; aw = bias[j0 + 3]; }
            else      { ax = ay = az = aw = 0.f; }
            #pragma unroll
            for (int i = 0; i < CIN; i++) {
                float4 w = *(const float4*)&Ws[i * COUT + j0];
                ax = fmaf(xr[i], w.x, ax); ay = fmaf(xr[i], w.y, ay);
                az = fmaf(xr[i], w.z, az); aw = fmaf(xr[i], w.w, aw);
            }
            float4 o; o.x = ax; o.y = ay; o.z = az; o.w = aw;
            *(float4*)&out[n * COUT + j0] = o;
        }
    } else {
        #pragma unroll
        for (int j = 0; j < COUT; j++) {
            float a = OUTY ? bias[j] : 0.f;
            #pragma unroll
            for (int i = 0; i < CIN; i++) a = fmaf(xr[i], Ws[i * COUT + j], a);
            out[n * COUT + j] = a;
        }
    }
}

// ---------------- BN stats: partials + last-block finalize ----------------
template <int C>
__global__ void k_redstats(const float* __restrict__ gamma, const float* __restrict__ beta) {
    constexpr int CP = (C > 4) ? C : 4;
    constexpr int RPB = 256 / CP;
    int c = threadIdx.x % CP;
    int r = threadIdx.x / CP;
    float s = 0.f, q = 0.f;
    if (c < C) {
        for (int n = blockIdx.x * RPB + r; n < NN; n += 256 * RPB) {
            float v = g_y[n * C + c];
            s += v; q = fmaf(v, v, q);
        }
    }
    __shared__ float ss[256], sq[256];
    ss[threadIdx.x] = s; sq[threadIdx.x] = q;
    __syncthreads();
    if (r == 0 && c < C) {
        for (int k = 1; k < RPB; k++) { s += ss[k * CP + c]; q += sq[k * CP + c]; }
        g_part[blockIdx.x * 128 + c]      = s;
        g_part[blockIdx.x * 128 + 64 + c] = q;
    }
    __threadfence();
    __syncthreads();
    __shared__ int lastf;
    if (threadIdx.x == 0) lastf = (atomicAdd(&g_rcount, 1) == 255) ? 1 : 0;
    __syncthreads();
    if (!lastf) return;

    // final reduction over 256 partial blocks
    int fc = threadIdx.x & 63;
    int fr = threadIdx.x >> 6;      // 0..3
    float fs = 0.f, fq = 0.f;
    if (fc < C) {
        for (int b = fr; b < 256; b += 4) {
            fs += g_part[b * 128 + fc];
            fq += g_part[b * 128 + 64 + fc];
        }
    }
    ss[threadIdx.x] = fs; sq[threadIdx.x] = fq;
    __syncthreads();
    if (fr == 0 && fc < C) {
        for (int k = 1; k < 4; k++) { fs += ss[k * 64 + fc]; fq += sq[k * 64 + fc]; }
        float mean = fs * (1.0f / NN);
        float var = fq * (1.0f / NN) - mean * mean;
        float sc = gamma[fc] * rsqrtf(var + BN_EPS);
        g_scale[fc] = sc;
        g_shift[fc] = beta[fc] - mean * sc;
    }
    if (threadIdx.x == 0) g_rcount = 0;   // self-reset for next use
}

// ---------------- BN apply + maxpool + lrelu + linear + lrelu ----------------
template <int C, int PK, int PP, bool TOOUT>
__global__ void k_post(const float* __restrict__ lw, const float* __restrict__ lb,
                       float* __restrict__ outp) {
    __shared__ __align__(16) float lws[C * C];
    __shared__ float lbs[C], sc[C], sh[C];
    for (int i = threadIdx.x; i < C * C; i += blockDim.x) lws[i] = lw[i];
    if (threadIdx.x < C) {
        lbs[threadIdx.x] = lb[threadIdx.x];
        sc[threadIdx.x]  = g_scale[threadIdx.x];
        sh[threadIdx.x]  = g_shift[threadIdx.x];
    }
    __syncthreads();
    int n = blockIdx.x * blockDim.x + threadIdx.x;
    if (n >= NN) return;
    float* out = TOOUT ? outp : g_x;

    float t[C];
    if constexpr (C % 4 == 0) {
        const float4* yv = (const float4*)&g_y[n * C];
        #pragma unroll
        for (int i = 0; i < C / 4; i++) {
            float4 v = yv[i];
            t[4 * i]     = fmaf(v.x, sc[4 * i],     sh[4 * i]);
            t[4 * i + 1] = fmaf(v.y, sc[4 * i + 1], sh[4 * i + 1]);
            t[4 * i + 2] = fmaf(v.z, sc[4 * i + 2], sh[4 * i + 2]);
            t[4 * i + 3] = fmaf(v.w, sc[4 * i + 3], sh[4 * i + 3]);
        }
    } else {
        #pragma unroll
        for (int c = 0; c < C; c++) t[c] = fmaf(g_y[n * C + c], sc[c], sh[c]);
    }

    float m[C];
    #pragma unroll
    for (int c = 0; c < C; c++) {
        int lo = c - PP; if (lo < 0) lo = 0;
        int hi = c - PP + PK - 1; if (hi > C - 1) hi = C - 1;
        float mx = t[lo];
        #pragma unroll
        for (int d = 0; d < PK; d++) {
            int idx = c - PP + d;
            if (idx > lo && idx <= hi) mx = fmaxf(mx, t[idx]);
        }
        m[c] = (mx >= 0.f) ? mx : SLOPE * mx;
    }

    if constexpr (C % 4 == 0) {
        for (int j0 = 0; j0 < C; j0 += 4) {
            float a0 = lbs[j0], a1 = lbs[j0 + 1], a2 = lbs[j0 + 2], a3 = lbs[j0 + 3];
            #pragma unroll
            for (int c = 0; c < C; c += 4) {
                float4 w0 = *(const float4*)&lws[(j0    ) * C + c];
                float4 w1 = *(const float4*)&lws[(j0 + 1) * C + c];
                float4 w2 = *(const float4*)&lws[(j0 + 2) * C + c];
                float4 w3 = *(const float4*)&lws[(j0 + 3) * C + c];
                a0 = fmaf(m[c], w0.x, a0); a0 = fmaf(m[c+1], w0.y, a0); a0 = fmaf(m[c+2], w0.z, a0); a0 = fmaf(m[c+3], w0.w, a0);
                a1 = fmaf(m[c], w1.x, a1); a1 = fmaf(m[c+1], w1.y, a1); a1 = fmaf(m[c+2], w1.z, a1); a1 = fmaf(m[c+3], w1.w, a1);
                a2 = fmaf(m[c], w2.x, a2); a2 = fmaf(m[c+1], w2.y, a2); a2 = fmaf(m[c+2], w2.z, a2); a2 = fmaf(m[c+3], w2.w, a2);
                a3 = fmaf(m[c], w3.x, a3); a3 = fmaf(m[c+1], w3.y, a3); a3 = fmaf(m[c+2], w3.z, a3); a3 = fmaf(m[c+3], w3.w, a3);
            }
            float4 o;
            o.x = (a0 >= 0.f) ? a0 : SLOPE * a0;
            o.y = (a1 >= 0.f) ? a1 : SLOPE * a1;
            o.z = (a2 >= 0.f) ? a2 : SLOPE * a2;
            o.w = (a3 >= 0.f) ? a3 : SLOPE * a3;
            *(float4*)&out[n * C + j0] = o;
        }
    } else {
        #pragma unroll
        for (int j = 0; j < C; j++) {
            float a = lbs[j];
            #pragma unroll
            for (int c = 0; c < C; c++) a = fmaf(m[c], lws[j * C + c], a);
            out[n * C + j] = (a >= 0.f) ? a : SLOPE * a;
        }
    }
}

// ---------------- launch ----------------
extern "C" void kernel_launch(void* const* d_in, const int* in_sizes, int n_in,
                              void* d_out, int out_size) {
    const float* x   = (const float*)d_in[0];
    const int*   ei  = (const int*)d_in[1];
    const int*   src = ei;
    const int*   dst = ei + NE;
    const float *w0 = (const float*)d_in[2],  *b0 = (const float*)d_in[3];
    const float *g0 = (const float*)d_in[4],  *bb0 = (const float*)d_in[5];
    const float *lw0 = (const float*)d_in[6], *lb0 = (const float*)d_in[7];
    const float *w1 = (const float*)d_in[8],  *b1 = (const float*)d_in[9];
    const float *g1 = (const float*)d_in[10], *bb1 = (const float*)d_in[11];
    const float *lw1 = (const float*)d_in[12], *lb1 = (const float*)d_in[13];
    const float *w2 = (const float*)d_in[14], *b2 = (const float*)d_in[15];
    const float *g2 = (const float*)d_in[16], *bb2 = (const float*)d_in[17];
    const float *lw2 = (const float*)d_in[18], *lb2 = (const float*)d_in[19];
    float* out = (float*)d_out;

    // CSR build
    k_zero<<<NBLK_N, 256>>>();
    k_hist<<<(NE / 4 + 255) / 256, 256>>>(dst);
    k_scan1<<<NB, SCAN_B>>>();
    k_scan2<<<1, 32>>>();
    k_scan3<<<NB, SCAN_B>>>();
    k_fill<<<NBLK_E, 256>>>(src, dst);

    // stage 0: aggregate x (3ch) first, then W0 (linearity of GCN conv)
    k_agg3<false><<<AGG_BLK, 256>>>(x, nullptr);                 // -> g_z
    k_mm<3, 64, 2, true><<<NBLK_N, 256>>>(nullptr, w0, b0);      // g_y = z@W0 + b0
    k_redstats<64><<<256, 256>>>(g0, bb0);
    k_post<64, 3, 1, false><<<NBLK_N, 256>>>(lw0, lb0, nullptr); // -> g_x

    // stage 1: 64 -> 64
    k_mm<64, 64, 1, false><<<NBLK_N, 256>>>(nullptr, w1, nullptr); // g_h = x@W1
    k_agg64<<<AGG_BLK, 256>>>(b1);                                 // -> g_y
    k_redstats<64><<<256, 256>>>(g1, bb1);
    k_post<64, 5, 2, false><<<NBLK_N, 256>>>(lw1, lb1, nullptr);   // -> g_x

    // stage 2: W2 first (64->3), then aggregate 3ch
    k_mm<64, 3, 1, false><<<NBLK_N, 256>>>(nullptr, w2, nullptr);  // g_h[N,3]
    k_agg3<true><<<AGG_BLK, 256>>>(nullptr, b2);                   // -> g_y (N,3)
    k_redstats<3><<<256, 256>>>(g2, bb2);
    k_post<3, 3, 1, true><<<NBLK_N, 256>>>(lw2, lb2, out);
}

// round 4
// speedup vs baseline: 1.2815x; 1.1251x over previous
#include <cuda_runtime.h>
#include <math_constants.h>

#define NN 80000
#define NE 1280000
#define NBLK_N ((NN + 255) / 256)         // 313
#define AGG_BLK ((NN * 32 + 255) / 256)   // 10000 (warp per node)
#define BN_EPS 1e-5f
#define SLOPE 0.01f

// ---------------- persistent device scratch ----------------
__device__ int   g_deg[NN];
__device__ int   g_cnt[NN];
__device__ int   g_rowptr[NN];
__device__ int   g_total = 0;
__device__ int   g_srcs[NE];
__device__ float g_dinv[NN];
__device__ __align__(16) float g_h[NN * 64];
__device__ __align__(16) float g_y[NN * 64];
__device__ __align__(16) float g_z[NN * 3];
__device__ float g_part[256 * 128];
__device__ float g_scale[64];
__device__ float g_shift[64];
__device__ int   g_rcount = 0;

// ---------------- CSR build ----------------
__global__ void k_zero() {
    int i = blockIdx.x * blockDim.x + threadIdx.x;
    if (i < NN) g_deg[i] = 0;
    if (i == 0) g_total = 0;
}

__global__ void k_hist(const int* __restrict__ dst) {
    int i = blockIdx.x * blockDim.x + threadIdx.x;
    if (i < NE / 4) {
        int4 d = ((const int4*)dst)[i];
        if ((unsigned)d.x < NN) atomicAdd(&g_deg[d.x], 1);
        if ((unsigned)d.y < NN) atomicAdd(&g_deg[d.y], 1);
        if ((unsigned)d.z < NN) atomicAdd(&g_deg[d.z], 1);
        if ((unsigned)d.w < NN) atomicAdd(&g_deg[d.w], 1);
    }
}

// order-free CSR slot allocation: each node gets a private contiguous range
__global__ void k_alloc() {
    int i = blockIdx.x * blockDim.x + threadIdx.x;
    if (i < NN) {
        int d = g_deg[i];
        g_dinv[i] = rsqrtf((float)d + 2.0f);
        int p = atomicAdd(&g_total, d);
        g_rowptr[i] = p;
        g_cnt[i] = p;
    }
}

__global__ void k_fill(const int* __restrict__ src,
                       const int* __restrict__ dst) {
    int i = blockIdx.x * blockDim.x + threadIdx.x;
    if (i < NE / 4) {
        int4 s4 = ((const int4*)src)[i];
        int4 d4 = ((const int4*)dst)[i];
        #pragma unroll
        for (int k = 0; k < 4; k++) {
            int s = (&s4.x)[k], d = (&d4.x)[k];
            if ((unsigned)d < NN && (unsigned)s < NN) {
                int p = atomicAdd(&g_cnt[d], 1);
                if ((unsigned)p < NE) g_srcs[p] = s;
            }
        }
    }
}

// ---------------- 3-channel aggregation (warp per node) ----------------
template <bool FROMH>
__global__ void k_agg3(const float* __restrict__ xin, const float* __restrict__ bias) {
    int gw = (blockIdx.x * blockDim.x + threadIdx.x) >> 5;
    int lane = threadIdx.x & 31;
    if (gw >= NN) return;
    const float* feat = FROMH ? (const float*)g_h : xin;

    int beg = g_rowptr[gw], end = beg + g_deg[gw];
    float a0 = 0.f, a1 = 0.f, a2 = 0.f;
    for (int e = beg + lane; e < end; e += 32) {
        int s = g_srcs[e];
        float w = g_dinv[s];
        a0 = fmaf(feat[s * 3 + 0], w, a0);
        a1 = fmaf(feat[s * 3 + 1], w, a1);
        a2 = fmaf(feat[s * 3 + 2], w, a2);
    }
    #pragma unroll
    for (int o = 16; o; o >>= 1) {
        a0 += __shfl_down_sync(0xffffffffu, a0, o);
        a1 += __shfl_down_sync(0xffffffffu, a1, o);
        a2 += __shfl_down_sync(0xffffffffu, a2, o);
    }
    if (lane == 0) {
        float dn = g_dinv[gw];
        float st = 2.f * dn * dn;
        float o0 = fmaf(a0, dn, st * feat[gw * 3 + 0]);
        float o1 = fmaf(a1, dn, st * feat[gw * 3 + 1]);
        float o2 = fmaf(a2, dn, st * feat[gw * 3 + 2]);
        if (FROMH) {
            g_y[gw * 3 + 0] = o0 + bias[0];
            g_y[gw * 3 + 1] = o1 + bias[1];
            g_y[gw * 3 + 2] = o2 + bias[2];
        } else {
            g_z[gw * 3 + 0] = o0;
            g_z[gw * 3 + 1] = o1;
            g_z[gw * 3 + 2] = o2;
        }
    }
}

// ---------------- 64-channel aggregation (warp per node, float2/lane) ----------------
__global__ void k_agg64(const float* __restrict__ bias) {
    int gw = (blockIdx.x * blockDim.x + threadIdx.x) >> 5;
    int lane = threadIdx.x & 31;
    if (gw >= NN) return;

    int beg = g_rowptr[gw], end = beg + g_deg[gw];
    float ax = 0.f, ay = 0.f;
    int e = beg;
    for (; e + 4 <= end; e += 4) {
        int s0 = g_srcs[e],     s1 = g_srcs[e + 1];
        int s2 = g_srcs[e + 2], s3 = g_srcs[e + 3];
        float w0 = g_dinv[s0], w1 = g_dinv[s1], w2 = g_dinv[s2], w3 = g_dinv[s3];
        float2 h0 = ((const float2*)&g_h[s0 * 64])[lane];
        float2 h1 = ((const float2*)&g_h[s1 * 64])[lane];
        float2 h2 = ((const float2*)&g_h[s2 * 64])[lane];
        float2 h3 = ((const float2*)&g_h[s3 * 64])[lane];
        ax = fmaf(h0.x, w0, ax); ay = fmaf(h0.y, w0, ay);
        ax = fmaf(h1.x, w1, ax); ay = fmaf(h1.y, w1, ay);
        ax = fmaf(h2.x, w2, ax); ay = fmaf(h2.y, w2, ay);
        ax = fmaf(h3.x, w3, ax); ay = fmaf(h3.y, w3, ay);
    }
    for (; e < end; e++) {
        int s = g_srcs[e];
        float w = g_dinv[s];
        float2 h = ((const float2*)&g_h[s * 64])[lane];
        ax = fmaf(h.x, w, ax); ay = fmaf(h.y, w, ay);
    }

    float dn = g_dinv[gw];
    float st = 2.f * dn * dn;
    float2 hs = ((const float2*)&g_h[gw * 64])[lane];
    float2 bv = ((const float2*)bias)[lane];
    float2 o;
    o.x = fmaf(ax, dn, fmaf(st, hs.x, bv.x));
    o.y = fmaf(ay, dn, fmaf(st, hs.y, bv.y));
    ((float2*)&g_y[gw * 64])[lane] = o;
}

// ---------------- BN finalize helper (inlined in the two stats kernels) ----------------
template <int C>
__device__ __forceinline__ void bn_finalize(float s, float q, int cslot, bool valid,
                                            const float* gamma, const float* beta,
                                            float* ss, float* sq, int rpb, int cp) {
    int tid = threadIdx.x;
    if (valid) {
        g_part[blockIdx.x * 128 + cslot]      = s;
        g_part[blockIdx.x * 128 + 64 + cslot] = q;
    }
    __threadfence();
    __syncthreads();
    __shared__ int lastf;
    if (tid == 0) lastf = (atomicAdd(&g_rcount, 1) == 255) ? 1 : 0;
    __syncthreads();
    if (!lastf) return;

    int fc = tid & 63;
    int fr = tid >> 6;
    float fs = 0.f, fq = 0.f;
    if (fc < C) {
        for (int b = fr; b < 256; b += 4) {
            fs += g_part[b * 128 + fc];
            fq += g_part[b * 128 + 64 + fc];
        }
    }
    ss[tid] = fs; sq[tid] = fq;
    __syncthreads();
    if (fr == 0 && fc < C) {
        for (int k = 1; k < 4; k++) { fs += ss[k * 64 + fc]; fq += sq[k * 64 + fc]; }
        float mean = fs * (1.0f / NN);
        float var = fq * (1.0f / NN) - mean * mean;
        float sc = gamma[fc] * rsqrtf(var + BN_EPS);
        g_scale[fc] = sc;
        g_shift[fc] = beta[fc] - mean * sc;
    }
    if (tid == 0) g_rcount = 0;
}

// ---------------- stage0: y = z@W0 + b0  fused with BN stats ----------------
__global__ void k_mmred(const float* __restrict__ W, const float* __restrict__ bias,
                        const float* __restrict__ gamma, const float* __restrict__ beta) {
    int c = threadIdx.x & 63;
    int r = threadIdx.x >> 6;    // 0..3
    float w0 = W[c], w1 = W[64 + c], w2 = W[128 + c], bv = bias[c];
    float s = 0.f, q = 0.f;
    for (int n = blockIdx.x * 4 + r; n < NN; n += 1024) {
        float z0 = g_z[n * 3 + 0], z1 = g_z[n * 3 + 1], z2 = g_z[n * 3 + 2];
        float y = fmaf(z0, w0, fmaf(z1, w1, fmaf(z2, w2, bv)));
        s += y; q = fmaf(y, y, q);
        g_y[n * 64 + c] = y;
    }
    __shared__ float ss[256], sq[256];
    ss[threadIdx.x] = s; sq[threadIdx.x] = q;
    __syncthreads();
    if (r == 0) {
        for (int k = 1; k < 4; k++) { s += ss[k * 64 + c]; q += sq[k * 64 + c]; }
    }
    bn_finalize<64>(s, q, c, r == 0, gamma, beta, ss, sq, 4, 64);
}

// ---------------- standalone BN stats (stage1: C=64, stage2: C=3) ----------------
template <int C>
__global__ void k_redstats(const float* __restrict__ gamma, const float* __restrict__ beta) {
    constexpr int CP = (C > 4) ? C : 4;
    constexpr int RPB = 256 / CP;
    int c = threadIdx.x % CP;
    int r = threadIdx.x / CP;
    float s = 0.f, q = 0.f;
    if (c < C) {
        for (int n = blockIdx.x * RPB + r; n < NN; n += 256 * RPB) {
            float v = g_y[n * C + c];
            s += v; q = fmaf(v, v, q);
        }
    }
    __shared__ float ss[256], sq[256];
    ss[threadIdx.x] = s; sq[threadIdx.x] = q;
    __syncthreads();
    if (r == 0 && c < C) {
        for (int k = 1; k < RPB; k++) { s += ss[k * CP + c]; q += sq[k * CP + c]; }
    }
    bn_finalize<C>(s, q, c, (r == 0 && c < C), gamma, beta, ss, sq, RPB, CP);
}

// ---------------- fused: BN apply + pool + lrelu + linear + lrelu + next W ----------------
// reads g_y[N,64], writes g_h[N,COUT2]
template <int PK, int PP, int COUT2>
__global__ __launch_bounds__(128) void k_postmm(const float* __restrict__ lw,
                                                const float* __restrict__ lb,
                                                const float* __restrict__ W2) {
    __shared__ __align__(16) float lws[64 * 64];
    __shared__ __align__(16) float w2s[64 * COUT2];
    __shared__ float lbs[64], sc[64], sh[64];
    int tid = threadIdx.x;
    for (int i = tid; i < 64 * 64; i += 128) lws[i] = lw[i];
    for (int i = tid; i < 64 * COUT2; i += 128) w2s[i] = W2[i];
    if (tid < 64) { lbs[tid] = lb[tid]; sc[tid] = g_scale[tid]; sh[tid] = g_shift[tid]; }
    __syncthreads();
    int n = blockIdx.x * 128 + tid;
    if (n >= NN) return;

    float t[64];
    {
        const float4* yv = (const float4*)&g_y[n * 64];
        #pragma unroll
        for (int i = 0; i < 16; i++) {
            float4 v = yv[i];
            t[4 * i]     = fmaf(v.x, sc[4 * i],     sh[4 * i]);
            t[4 * i + 1] = fmaf(v.y, sc[4 * i + 1], sh[4 * i + 1]);
            t[4 * i + 2] = fmaf(v.z, sc[4 * i + 2], sh[4 * i + 2]);
            t[4 * i + 3] = fmaf(v.w, sc[4 * i + 3], sh[4 * i + 3]);
        }
    }

    float m[64];
    #pragma unroll
    for (int c = 0; c < 64; c++) {
        int lo = c - PP; if (lo < 0) lo = 0;
        int hi = c - PP + PK - 1; if (hi > 63) hi = 63;
        float mx = t[lo];
        #pragma unroll
        for (int d = 0; d < PK; d++) {
            int idx = c - PP + d;
            if (idx > lo && idx <= hi) mx = fmaxf(mx, t[idx]);
        }
        m[c] = (mx >= 0.f) ? mx : SLOPE * mx;
    }

    float r[64];
    #pragma unroll 4
    for (int j0 = 0; j0 < 64; j0 += 4) {
        float a0 = lbs[j0], a1 = lbs[j0 + 1], a2 = lbs[j0 + 2], a3 = lbs[j0 + 3];
        #pragma unroll
        for (int c = 0; c < 64; c += 4) {
            float4 q0 = *(const float4*)&lws[(j0    ) * 64 + c];
            float4 q1 = *(const float4*)&lws[(j0 + 1) * 64 + c];
            float4 q2 = *(const float4*)&lws[(j0 + 2) * 64 + c];
            float4 q3 = *(const float4*)&lws[(j0 + 3) * 64 + c];
            a0 = fmaf(m[c], q0.x, a0); a0 = fmaf(m[c+1], q0.y, a0); a0 = fmaf(m[c+2], q0.z, a0); a0 = fmaf(m[c+3], q0.w, a0);
            a1 = fmaf(m[c], q1.x, a1); a1 = fmaf(m[c+1], q1.y, a1); a1 = fmaf(m[c+2], q1.z, a1); a1 = fmaf(m[c+3], q1.w, a1);
            a2 = fmaf(m[c], q2.x, a2); a2 = fmaf(m[c+1], q2.y, a2); a2 = fmaf(m[c+2], q2.z, a2); a2 = fmaf(m[c+3], q2.w, a2);
            a3 = fmaf(m[c], q3.x, a3); a3 = fmaf(m[c+1], q3.y, a3); a3 = fmaf(m[c+2], q3.z, a3); a3 = fmaf(m[c+3], q3.w, a3);
        }
        r[j0]     = (a0 >= 0.f) ? a0 : SLOPE * a0;
        r[j0 + 1] = (a1 >= 0.f) ? a1 : SLOPE * a1;
        r[j0 + 2] = (a2 >= 0.f) ? a2 : SLOPE * a2;
        r[j0 + 3] = (a3 >= 0.f) ? a3 : SLOPE * a3;
    }

    // second matmul: out = r @ W2, W2 is (64, COUT2) row-major
    if constexpr (COUT2 % 4 == 0) {
        #pragma unroll 4
        for (int j0 = 0; j0 < COUT2; j0 += 4) {
            float a0 = 0.f, a1 = 0.f, a2 = 0.f, a3 = 0.f;
            #pragma unroll
            for (int c = 0; c < 64; c++) {
                float4 w = *(const float4*)&w2s[c * COUT2 + j0];
                a0 = fmaf(r[c], w.x, a0); a1 = fmaf(r[c], w.y, a1);
                a2 = fmaf(r[c], w.z, a2); a3 = fmaf(r[c], w.w, a3);
            }
            float4 o; o.x = a0; o.y = a1; o.z = a2; o.w = a3;
            *(float4*)&g_h[n * COUT2 + j0] = o;
        }
    } else {
        float a0 = 0.f, a1 = 0.f, a2 = 0.f;
        #pragma unroll
        for (int c = 0; c < 64; c++) {
            float rc = r[c];
            a0 = fmaf(rc, w2s[c * COUT2 + 0], a0);
            a1 = fmaf(rc, w2s[c * COUT2 + 1], a1);
            a2 = fmaf(rc, w2s[c * COUT2 + 2], a2);
        }
        g_h[n * COUT2 + 0] = a0; g_h[n * COUT2 + 1] = a1; g_h[n * COUT2 + 2] = a2;
    }
}

// ---------------- final stage post (C=3) -> d_out ----------------
__global__ void k_post3(const float* __restrict__ lw, const float* __restrict__ lb,
                        float* __restrict__ outp) {
    __shared__ float lws[9], lbs[3], sc[3], sh[3];
    if (threadIdx.x < 9) lws[threadIdx.x] = lw[threadIdx.x];
    if (threadIdx.x < 3) {
        lbs[threadIdx.x] = lb[threadIdx.x];
        sc[threadIdx.x]  = g_scale[threadIdx.x];
        sh[threadIdx.x]  = g_shift[threadIdx.x];
    }
    __syncthreads();
    int n = blockIdx.x * blockDim.x + threadIdx.x;
    if (n >= NN) return;

    float t0 = fmaf(g_y[n * 3 + 0], sc[0], sh[0]);
    float t1 = fmaf(g_y[n * 3 + 1], sc[1], sh[1]);
    float t2 = fmaf(g_y[n * 3 + 2], sc[2], sh[2]);
    // maxpool k=3 p=1 over 3 channels
    float m0 = fmaxf(t0, t1);
    float m1 = fmaxf(m0, t2);
    float m2 = fmaxf(t1, t2);
    m0 = (m0 >= 0.f) ? m0 : SLOPE * m0;
    m1 = (m1 >= 0.f) ? m1 : SLOPE * m1;
    m2 = (m2 >= 0.f) ? m2 : SLOPE * m2;
    #pragma unroll
    for (int j = 0; j < 3; j++) {
        float a = lbs[j];
        a = fmaf(m0, lws[j * 3 + 0], a);
        a = fmaf(m1, lws[j * 3 + 1], a);
        a = fmaf(m2, lws[j * 3 + 2], a);
        outp[n * 3 + j] = (a >= 0.f) ? a : SLOPE * a;
    }
}

// ---------------- launch ----------------
extern "C" void kernel_launch(void* const* d_in, const int* in_sizes, int n_in,
                              void* d_out, int out_size) {
    const float* x   = (const float*)d_in[0];
    const int*   ei  = (const int*)d_in[1];
    const int*   src = ei;
    const int*   dst = ei + NE;
    const float *w0 = (const float*)d_in[2],  *b0 = (const float*)d_in[3];
    const float *g0 = (const float*)d_in[4],  *bb0 = (const float*)d_in[5];
    const float *lw0 = (const float*)d_in[6], *lb0 = (const float*)d_in[7];
    const float *w1 = (const float*)d_in[8],  *b1 = (const float*)d_in[9];
    const float *g1 = (const float*)d_in[10], *bb1 = (const float*)d_in[11];
    const float *lw1 = (const float*)d_in[12], *lb1 = (const float*)d_in[13];
    const float *w2 = (const float*)d_in[14], *b2 = (const float*)d_in[15];
    const float *g2 = (const float*)d_in[16], *bb2 = (const float*)d_in[17];
    const float *lw2 = (const float*)d_in[18], *lb2 = (const float*)d_in[19];
    float* out = (float*)d_out;

    // CSR build (scan-free)
    k_zero<<<NBLK_N, 256>>>();
    k_hist<<<(NE / 4 + 255) / 256, 256>>>(dst);
    k_alloc<<<NBLK_N, 256>>>();
    k_fill<<<(NE / 4 + 255) / 256, 256>>>(src, dst);

    // stage 0: aggregate raw x (3 ch), then fused mm+BNstats, then fused post+W1
    k_agg3<false><<<AGG_BLK, 256>>>(x, nullptr);                  // -> g_z
    k_mmred<<<256, 256>>>(w0, b0, g0, bb0);                       // -> g_y, scale/shift
    k_postmm<3, 1, 64><<<(NN + 127) / 128, 128>>>(lw0, lb0, w1);  // -> g_h = post0 @ W1

    // stage 1
    k_agg64<<<AGG_BLK, 256>>>(b1);                                // -> g_y
    k_redstats<64><<<256, 256>>>(g1, bb1);
    k_postmm<5, 2, 3><<<(NN + 127) / 128, 128>>>(lw1, lb1, w2);   // -> g_h[N,3] = post1 @ W2

    // stage 2
    k_agg3<true><<<AGG_BLK, 256>>>(nullptr, b2);                  // -> g_y[N,3]
    k_redstats<3><<<256, 256>>>(g2, bb2);
    k_post3<<<NBLK_N, 256>>>(lw2, lb2, out);
}